// round 8
// baseline (speedup 1.0000x reference)
#include <cuda_runtime.h>
#include <cstddef>
#include <cstdint>

#define N_NODES 100000
#define N_EDGES 1600000
#define IN_F    48
#define EDGE_F  32
#define CAT_F   96
#define HID_F   128
#define OUT_F   64

#define SCAN_T  1024
#define CHUNK   ((N_NODES + SCAN_T - 1) / SCAN_T)

__device__ int   g_deg_i [N_NODES];
__device__ int   g_rowptr[N_NODES + 1];
__device__ int   g_cursor[N_NODES];
__device__ int   g_csr_eid[N_EDGES];
__device__ int   g_csr_src[N_EDGES];
__device__ float g_msg [(size_t)N_EDGES * IN_F];
__device__ float g_h   [(size_t)N_NODES * CAT_F];
__device__ float g_hn1 [(size_t)N_NODES * CAT_F];
__device__ float g_h1  [(size_t)N_NODES * HID_F];
__device__ float g_z   [(size_t)N_NODES * 128];   // [self(64) | neigh(64)] pre-agg

// ---------------- CSR build ----------------
__global__ void k_zero_hist() {
    int i = blockIdx.x * blockDim.x + threadIdx.x;
    if (i < N_NODES) g_deg_i[i] = 0;
}

__global__ void __launch_bounds__(256) k_hist(const int* __restrict__ dst) {
    int e = blockIdx.x * blockDim.x + threadIdx.x;
    if (e < N_EDGES) atomicAdd(&g_deg_i[dst[e]], 1);
}

__global__ void __launch_bounds__(SCAN_T) k_scan() {
    __shared__ int sh[SCAN_T];
    int t = threadIdx.x;
    int start = t * CHUNK;
    int end = start + CHUNK; if (end > N_NODES) end = N_NODES;
    int s = 0;
    if (start < N_NODES) for (int i = start; i < end; i++) s += g_deg_i[i];
    sh[t] = s;
    __syncthreads();
    for (int d = 1; d < SCAN_T; d <<= 1) {
        int v = (t >= d) ? sh[t - d] : 0;
        __syncthreads();
        sh[t] += v;
        __syncthreads();
    }
    int off = sh[t] - s;
    if (start < N_NODES) {
        for (int i = start; i < end; i++) {
            g_rowptr[i] = off;
            g_cursor[i] = off;
            off += g_deg_i[i];
        }
        if (end == N_NODES) g_rowptr[N_NODES] = off;
    }
}

__global__ void __launch_bounds__(256) k_place(const int* __restrict__ src,
                                               const int* __restrict__ dst) {
    int e = blockIdx.x * blockDim.x + threadIdx.x;
    if (e >= N_EDGES) return;
    int p = atomicAdd(&g_cursor[dst[e]], 1);
    g_csr_eid[p] = e;
    g_csr_src[p] = src[e];
}

// ---------------- edge MLP in CSR order ----------------
__global__ void __launch_bounds__(256) k_edge_mlp(const float* __restrict__ efeat,
                                                  const float* __restrict__ nfeat,
                                                  const float* __restrict__ We,
                                                  const float* __restrict__ be) {
    __shared__ __align__(16) float sWe[EDGE_F * IN_F];
    __shared__ float sbe[IN_F];
    for (int i = threadIdx.x; i < EDGE_F * IN_F; i += blockDim.x) sWe[i] = We[i];
    for (int i = threadIdx.x; i < IN_F; i += blockDim.x) sbe[i] = be[i];
    __syncthreads();

    int p = blockIdx.x * blockDim.x + threadIdx.x;
    if (p >= N_EDGES) return;
    int eid = g_csr_eid[p];
    int s   = g_csr_src[p];

    float ef[EDGE_F];
    const float4* ep = (const float4*)(efeat + (size_t)eid * EDGE_F);
    #pragma unroll
    for (int i = 0; i < EDGE_F / 4; i++) {
        float4 v = ep[i];
        ef[4*i+0] = v.x; ef[4*i+1] = v.y; ef[4*i+2] = v.z; ef[4*i+3] = v.w;
    }

    const float4* np = (const float4*)(nfeat + (size_t)s * IN_F);
    float4*       op = (float4*)(g_msg + (size_t)p * IN_F);

    #pragma unroll 1
    for (int j = 0; j < IN_F / 4; j++) {
        float4 a;
        a.x = sbe[4*j+0]; a.y = sbe[4*j+1]; a.z = sbe[4*j+2]; a.w = sbe[4*j+3];
        #pragma unroll
        for (int k = 0; k < EDGE_F; k++) {
            float4 w = *(const float4*)&sWe[k * IN_F + 4*j];
            a.x = fmaf(ef[k], w.x, a.x);
            a.y = fmaf(ef[k], w.y, a.y);
            a.z = fmaf(ef[k], w.z, a.z);
            a.w = fmaf(ef[k], w.w, a.w);
        }
        a.x = fmaxf(a.x, 0.f); a.y = fmaxf(a.y, 0.f);
        a.z = fmaxf(a.z, 0.f); a.w = fmaxf(a.w, 0.f);
        float4 nf = np[j];
        a.x *= nf.x; a.y *= nf.y; a.z *= nf.z; a.w *= nf.w;
        op[j] = a;
    }
}

// ---------------- gather0: h = [nfeat | mean(msg)] ----------------
__global__ void __launch_bounds__(256) k_gather0(const float* __restrict__ nfeat) {
    int gw   = (blockIdx.x * 256 + threadIdx.x) >> 5;
    int lane = threadIdx.x & 31;
    int half = lane >> 4, sub = lane & 15;
    int node = gw * 2 + half;
    if (node >= N_NODES) return;
    bool active = sub < (IN_F / 4);

    int lo = g_rowptr[node], hi = g_rowptr[node + 1];
    float4 a0 = make_float4(0.f,0.f,0.f,0.f), a1 = make_float4(0.f,0.f,0.f,0.f);
    if (active) {
        int p = lo;
        for (; p + 1 < hi; p += 2) {
            float4 v0 = *(const float4*)(g_msg + (size_t)p       * IN_F + sub * 4);
            float4 v1 = *(const float4*)(g_msg + (size_t)(p + 1) * IN_F + sub * 4);
            a0.x += v0.x; a0.y += v0.y; a0.z += v0.z; a0.w += v0.w;
            a1.x += v1.x; a1.y += v1.y; a1.z += v1.z; a1.w += v1.w;
        }
        if (p < hi) {
            float4 v = *(const float4*)(g_msg + (size_t)p * IN_F + sub * 4);
            a0.x += v.x; a0.y += v.y; a0.z += v.z; a0.w += v.w;
        }
    }
    if (active) {
        float invd = 1.0f / fmaxf((float)(hi - lo), 1.0f);
        float4 nf = *(const float4*)(nfeat + (size_t)node * IN_F + sub * 4);
        *(float4*)(g_h + (size_t)node * CAT_F + sub * 4) = nf;
        float4 acc;
        acc.x = (a0.x + a1.x) * invd; acc.y = (a0.y + a1.y) * invd;
        acc.z = (a0.z + a1.z) * invd; acc.w = (a0.w + a1.w) * invd;
        *(float4*)(g_h + (size_t)node * CAT_F + IN_F + sub * 4) = acc;
    }
}

// ---------------- gather1: hn1 = mean(h[src]) ----------------
__global__ void __launch_bounds__(256) k_gather_h() {
    int node = (blockIdx.x * 256 + threadIdx.x) >> 5;
    int lane = threadIdx.x & 31;
    if (node >= N_NODES) return;
    bool active = lane < (CAT_F / 4);

    int lo = g_rowptr[node], hi = g_rowptr[node + 1];
    float4 a0 = make_float4(0.f,0.f,0.f,0.f), a1 = make_float4(0.f,0.f,0.f,0.f);
    int p = lo;
    for (; p + 1 < hi; p += 2) {
        int s0 = g_csr_src[p], s1 = g_csr_src[p + 1];
        if (active) {
            float4 v0 = *(const float4*)(g_h + (size_t)s0 * CAT_F + lane * 4);
            float4 v1 = *(const float4*)(g_h + (size_t)s1 * CAT_F + lane * 4);
            a0.x += v0.x; a0.y += v0.y; a0.z += v0.z; a0.w += v0.w;
            a1.x += v1.x; a1.y += v1.y; a1.z += v1.z; a1.w += v1.w;
        }
    }
    if (p < hi) {
        int s = g_csr_src[p];
        if (active) {
            float4 v = *(const float4*)(g_h + (size_t)s * CAT_F + lane * 4);
            a0.x += v.x; a0.y += v.y; a0.z += v.z; a0.w += v.w;
        }
    }
    if (active) {
        float invd = 1.0f / fmaxf((float)(hi - lo), 1.0f);
        float4 acc;
        acc.x = (a0.x + a1.x) * invd; acc.y = (a0.y + a1.y) * invd;
        acc.z = (a0.z + a1.z) * invd; acc.w = (a0.w + a1.w) * invd;
        *(float4*)(g_hn1 + (size_t)node * CAT_F + lane * 4) = acc;
    }
}

// ================= tf32 3x-split mma.sync GEMM =================
// C[M=64/block, N=128] = A[*,K] @ B[K,128]; K chunked by 64.
#define SA_STR 68
#define SB_STR 132
#define OFF_AH 0
#define OFF_AL (OFF_AH + 64 * SA_STR)
#define OFF_BH (OFF_AL + 64 * SA_STR)
#define OFF_BL (OFF_BH + 64 * SB_STR)
#define MMA_SMEM_FLOATS (OFF_BL + 64 * SB_STR)      // 25600
#define MMA_SMEM_BYTES  (MMA_SMEM_FLOATS * 4)       // 102400

static __device__ __forceinline__ uint32_t f2tf32(float x) {
    uint32_t r;
    asm("cvt.rna.tf32.f32 %0, %1;" : "=r"(r) : "f"(x));
    return r;
}
static __device__ __forceinline__ void split2(float x, float& hi, float& lo) {
    uint32_t h = f2tf32(x);
    hi = __uint_as_float(h);
    lo = __uint_as_float(f2tf32(x - hi));
}
static __device__ __forceinline__ void mma8(float* d, const uint32_t* a, uint32_t b0, uint32_t b1) {
    asm volatile(
        "mma.sync.aligned.m16n8k8.row.col.f32.tf32.tf32.f32 "
        "{%0,%1,%2,%3}, {%4,%5,%6,%7}, {%8,%9}, {%0,%1,%2,%3};"
        : "+f"(d[0]), "+f"(d[1]), "+f"(d[2]), "+f"(d[3])
        : "r"(a[0]), "r"(a[1]), "r"(a[2]), "r"(a[3]), "r"(b0), "r"(b1));
}

// MODE 0: sage1  A=[h|hn1] K=192, B=[W1s;W1n], out=relu(.+b1)->g_h1
// MODE 1: sage2  A=g_h1 K=128,    B=[W2s|W2n], out raw ->g_z
template <int KTOT, int MODE>
__global__ void __launch_bounds__(128) k_mma(const float* __restrict__ Wa,
                                             const float* __restrict__ Wb,
                                             const float* __restrict__ bias) {
    extern __shared__ float sm[];
    int tid  = threadIdx.x;
    int warp = tid >> 5, lane = tid & 31;
    int gid  = lane >> 2, qid = lane & 3;
    int node0 = blockIdx.x * 64;

    float d[16][4];
    #pragma unroll
    for (int nb = 0; nb < 16; nb++) { d[nb][0]=0.f; d[nb][1]=0.f; d[nb][2]=0.f; d[nb][3]=0.f; }

    const int NCH = KTOT / 64;
    #pragma unroll 1
    for (int kc = 0; kc < NCH; kc++) {
        __syncthreads();
        // ---- load A chunk: 64 rows x 64 cols, split hi/lo ----
        {
            int row = tid >> 1;
            int cb  = (tid & 1) * 32;
            int node = node0 + row;
            bool valid = node < N_NODES;
            #pragma unroll
            for (int q = 0; q < 8; q++) {
                int col = cb + q * 4;
                int cg  = kc * 64 + col;
                float4 v = make_float4(0.f, 0.f, 0.f, 0.f);
                if (valid) {
                    if (MODE == 0) {
                        v = (cg < 96)
                          ? *(const float4*)(g_h   + (size_t)node * CAT_F + cg)
                          : *(const float4*)(g_hn1 + (size_t)node * CAT_F + (cg - 96));
                    } else {
                        v = *(const float4*)(g_h1 + (size_t)node * HID_F + cg);
                    }
                }
                float hx,lx,hy,ly,hz,lz,hw,lw;
                split2(v.x,hx,lx); split2(v.y,hy,ly); split2(v.z,hz,lz); split2(v.w,hw,lw);
                float* ah = sm + OFF_AH + row * SA_STR + col;
                float* al = sm + OFF_AL + row * SA_STR + col;
                ah[0]=hx; ah[1]=hy; ah[2]=hz; ah[3]=hw;
                al[0]=lx; al[1]=ly; al[2]=lz; al[3]=lw;
            }
        }
        // ---- load B chunk: 64 rows(k) x 128 cols(n), split hi/lo ----
        {
            int row = tid >> 1;
            int cb  = (tid & 1) * 64;
            int kg  = kc * 64 + row;
            #pragma unroll
            for (int q = 0; q < 16; q++) {
                int col = cb + q * 4;
                float4 v;
                if (MODE == 0) {
                    v = (kg < 96)
                      ? *(const float4*)(Wa + (size_t)kg * 128 + col)
                      : *(const float4*)(Wb + (size_t)(kg - 96) * 128 + col);
                } else {
                    v = (col < 64)
                      ? *(const float4*)(Wa + (size_t)kg * 64 + col)
                      : *(const float4*)(Wb + (size_t)kg * 64 + (col - 64));
                }
                float hx,lx,hy,ly,hz,lz,hw,lw;
                split2(v.x,hx,lx); split2(v.y,hy,ly); split2(v.z,hz,lz); split2(v.w,hw,lw);
                float* bh = sm + OFF_BH + row * SB_STR + col;
                float* bl = sm + OFF_BL + row * SB_STR + col;
                bh[0]=hx; bh[1]=hy; bh[2]=hz; bh[3]=hw;
                bl[0]=lx; bl[1]=ly; bl[2]=lz; bl[3]=lw;
            }
        }
        __syncthreads();

        // ---- compute: 8 k-steps of 8 ----
        int wr = warp * 16;
        #pragma unroll 1
        for (int kk = 0; kk < 8; kk++) {
            int k0 = kk * 8;
            uint32_t ah[4], al[4];
            {
                const float* pAh = sm + OFF_AH + (wr + gid) * SA_STR + k0 + qid;
                const float* pAl = sm + OFF_AL + (wr + gid) * SA_STR + k0 + qid;
                ah[0] = __float_as_uint(pAh[0]);
                ah[1] = __float_as_uint(pAh[8 * SA_STR]);
                ah[2] = __float_as_uint(pAh[4]);
                ah[3] = __float_as_uint(pAh[8 * SA_STR + 4]);
                al[0] = __float_as_uint(pAl[0]);
                al[1] = __float_as_uint(pAl[8 * SA_STR]);
                al[2] = __float_as_uint(pAl[4]);
                al[3] = __float_as_uint(pAl[8 * SA_STR + 4]);
            }
            const float* pBh = sm + OFF_BH + (k0 + qid) * SB_STR + gid;
            const float* pBl = sm + OFF_BL + (k0 + qid) * SB_STR + gid;
            #pragma unroll
            for (int nb = 0; nb < 16; nb++) {
                uint32_t bh0 = __float_as_uint(pBh[nb * 8]);
                uint32_t bh1 = __float_as_uint(pBh[nb * 8 + 4 * SB_STR]);
                uint32_t bl0 = __float_as_uint(pBl[nb * 8]);
                uint32_t bl1 = __float_as_uint(pBl[nb * 8 + 4 * SB_STR]);
                mma8(d[nb], ah, bh0, bh1);
                mma8(d[nb], al, bh0, bh1);
                mma8(d[nb], ah, bl0, bl1);
            }
        }
    }

    // ---- epilogue ----
    int wr = warp * 16;
    int r0 = node0 + wr + gid;
    int r1 = r0 + 8;
    #pragma unroll
    for (int nb = 0; nb < 16; nb++) {
        int col = nb * 8 + qid * 2;
        if (MODE == 0) {
            float b0 = bias[col], b1v = bias[col + 1];
            if (r0 < N_NODES) {
                float2 o; o.x = fmaxf(d[nb][0] + b0, 0.f); o.y = fmaxf(d[nb][1] + b1v, 0.f);
                *(float2*)(g_h1 + (size_t)r0 * HID_F + col) = o;
            }
            if (r1 < N_NODES) {
                float2 o; o.x = fmaxf(d[nb][2] + b0, 0.f); o.y = fmaxf(d[nb][3] + b1v, 0.f);
                *(float2*)(g_h1 + (size_t)r1 * HID_F + col) = o;
            }
        } else {
            if (r0 < N_NODES) {
                float2 o; o.x = d[nb][0]; o.y = d[nb][1];
                *(float2*)(g_z + (size_t)r0 * 128 + col) = o;
            }
            if (r1 < N_NODES) {
                float2 o; o.x = d[nb][2]; o.y = d[nb][3];
                *(float2*)(g_z + (size_t)r1 * 128 + col) = o;
            }
        }
    }
}

// ---------------- sage2 gather epilogue: out = zs + mean(zn[src]) + b2 ----------------
__global__ void __launch_bounds__(256) k_sage2_gather(const float* __restrict__ b2,
                                                      float* __restrict__ out) {
    int node = (blockIdx.x * 256 + threadIdx.x) >> 5;
    int lane = threadIdx.x & 31;
    if (node >= N_NODES) return;
    int c = lane * 2;

    float2 zs = *(const float2*)(g_z + (size_t)node * 128 + c);

    int lo = g_rowptr[node], hi = g_rowptr[node + 1];
    float2 a0 = make_float2(0.f, 0.f), a1 = make_float2(0.f, 0.f);
    int p = lo;
    for (; p + 1 < hi; p += 2) {
        int s0 = g_csr_src[p], s1 = g_csr_src[p + 1];
        float2 v0 = *(const float2*)(g_z + (size_t)s0 * 128 + 64 + c);
        float2 v1 = *(const float2*)(g_z + (size_t)s1 * 128 + 64 + c);
        a0.x += v0.x; a0.y += v0.y;
        a1.x += v1.x; a1.y += v1.y;
    }
    if (p < hi) {
        int s = g_csr_src[p];
        float2 v = *(const float2*)(g_z + (size_t)s * 128 + 64 + c);
        a0.x += v.x; a0.y += v.y;
    }
    float invd = 1.0f / fmaxf((float)(hi - lo), 1.0f);
    float2 b = *(const float2*)(b2 + c);
    float2 r;
    r.x = zs.x + (a0.x + a1.x) * invd + b.x;
    r.y = zs.y + (a0.y + a1.y) * invd + b.y;
    *(float2*)(out + (size_t)node * OUT_F + c) = r;
}

extern "C" void kernel_launch(void* const* d_in, const int* in_sizes, int n_in,
                              void* d_out, int out_size) {
    const float* nfeat = (const float*)d_in[0];
    const float* efeat = (const float*)d_in[1];
    const int*   src   = (const int*)  d_in[2];
    const int*   dst   = (const int*)  d_in[3];
    const float* We    = (const float*)d_in[4];
    const float* be    = (const float*)d_in[5];
    const float* W1s   = (const float*)d_in[6];
    const float* W1n   = (const float*)d_in[7];
    const float* b1    = (const float*)d_in[8];
    const float* W2s   = (const float*)d_in[9];
    const float* W2n   = (const float*)d_in[10];
    const float* b2    = (const float*)d_in[11];
    float* out = (float*)d_out;

    const int TPB = 256;
    const int edge_blocks = (N_EDGES + TPB - 1) / TPB;
    const int node_blocks = (N_NODES + TPB - 1) / TPB;
    const int g0_blocks   = (N_NODES + 15) / 16;
    const int gw_blocks   = (N_NODES + 7) / 8;
    const int mma_blocks  = (N_NODES + 63) / 64;   // 1563

    cudaFuncSetAttribute(k_mma<192, 0>, cudaFuncAttributeMaxDynamicSharedMemorySize, MMA_SMEM_BYTES);
    cudaFuncSetAttribute(k_mma<128, 1>, cudaFuncAttributeMaxDynamicSharedMemorySize, MMA_SMEM_BYTES);

    k_zero_hist<<<node_blocks, TPB>>>();
    k_hist     <<<edge_blocks, TPB>>>(dst);
    k_scan     <<<1, SCAN_T>>>();
    k_place    <<<edge_blocks, TPB>>>(src, dst);
    k_edge_mlp <<<edge_blocks, TPB>>>(efeat, nfeat, We, be);
    k_gather0  <<<g0_blocks, TPB>>>(nfeat);
    k_gather_h <<<gw_blocks, TPB>>>();
    k_mma<192, 0><<<mma_blocks, 128, MMA_SMEM_BYTES>>>(W1s, W1n, b1);
    k_mma<128, 1><<<mma_blocks, 128, MMA_SMEM_BYTES>>>(W2s, W2n, nullptr);
    k_sage2_gather<<<gw_blocks, TPB>>>(b2, out);
}

// round 9
// speedup vs baseline: 1.0848x; 1.0848x over previous
#include <cuda_runtime.h>
#include <cstddef>
#include <cstdint>

#define N_NODES 100000
#define N_EDGES 1600000
#define IN_F    48
#define EDGE_F  32
#define CAT_F   96
#define HID_F   128
#define OUT_F   64

#define SCAN_T  1024
#define CHUNK   ((N_NODES + SCAN_T - 1) / SCAN_T)

__device__ int   g_deg_i [N_NODES];
__device__ int   g_rowptr[N_NODES + 1];
__device__ int   g_cursor[N_NODES];
__device__ int   g_csr_eid[N_EDGES];
__device__ int   g_csr_src[N_EDGES];
__device__ float g_msg [(size_t)N_EDGES * IN_F];
__device__ float g_h   [(size_t)N_NODES * CAT_F];
__device__ float g_hn1 [(size_t)N_NODES * CAT_F];
__device__ float g_h1  [(size_t)N_NODES * HID_F];
__device__ float g_z2  [(size_t)N_NODES * OUT_F];

// ---------------- CSR build ----------------
__global__ void k_zero_hist() {
    int i = blockIdx.x * blockDim.x + threadIdx.x;
    if (i < N_NODES) g_deg_i[i] = 0;
}

__global__ void __launch_bounds__(256) k_hist(const int* __restrict__ dst) {
    int e = blockIdx.x * blockDim.x + threadIdx.x;
    if (e < N_EDGES) atomicAdd(&g_deg_i[dst[e]], 1);
}

__global__ void __launch_bounds__(SCAN_T) k_scan() {
    __shared__ int sh[SCAN_T];
    int t = threadIdx.x;
    int start = t * CHUNK;
    int end = start + CHUNK; if (end > N_NODES) end = N_NODES;
    int s = 0;
    if (start < N_NODES) for (int i = start; i < end; i++) s += g_deg_i[i];
    sh[t] = s;
    __syncthreads();
    for (int d = 1; d < SCAN_T; d <<= 1) {
        int v = (t >= d) ? sh[t - d] : 0;
        __syncthreads();
        sh[t] += v;
        __syncthreads();
    }
    int off = sh[t] - s;
    if (start < N_NODES) {
        for (int i = start; i < end; i++) {
            g_rowptr[i] = off;
            g_cursor[i] = off;
            off += g_deg_i[i];
        }
        if (end == N_NODES) g_rowptr[N_NODES] = off;
    }
}

__global__ void __launch_bounds__(256) k_place(const int* __restrict__ src,
                                               const int* __restrict__ dst) {
    int e = blockIdx.x * blockDim.x + threadIdx.x;
    if (e >= N_EDGES) return;
    int p = atomicAdd(&g_cursor[dst[e]], 1);
    g_csr_eid[p] = e;
    g_csr_src[p] = src[e];
}

// ---------------- edge MLP in CSR order ----------------
__global__ void __launch_bounds__(256) k_edge_mlp(const float* __restrict__ efeat,
                                                  const float* __restrict__ nfeat,
                                                  const float* __restrict__ We,
                                                  const float* __restrict__ be) {
    __shared__ __align__(16) float sWe[EDGE_F * IN_F];
    __shared__ float sbe[IN_F];
    for (int i = threadIdx.x; i < EDGE_F * IN_F; i += blockDim.x) sWe[i] = We[i];
    for (int i = threadIdx.x; i < IN_F; i += blockDim.x) sbe[i] = be[i];
    __syncthreads();

    int p = blockIdx.x * blockDim.x + threadIdx.x;
    if (p >= N_EDGES) return;
    int eid = g_csr_eid[p];
    int s   = g_csr_src[p];

    float ef[EDGE_F];
    const float4* ep = (const float4*)(efeat + (size_t)eid * EDGE_F);
    #pragma unroll
    for (int i = 0; i < EDGE_F / 4; i++) {
        float4 v = ep[i];
        ef[4*i+0] = v.x; ef[4*i+1] = v.y; ef[4*i+2] = v.z; ef[4*i+3] = v.w;
    }

    const float4* np = (const float4*)(nfeat + (size_t)s * IN_F);
    float4*       op = (float4*)(g_msg + (size_t)p * IN_F);

    #pragma unroll 1
    for (int j = 0; j < IN_F / 4; j++) {
        float4 a;
        a.x = sbe[4*j+0]; a.y = sbe[4*j+1]; a.z = sbe[4*j+2]; a.w = sbe[4*j+3];
        #pragma unroll
        for (int k = 0; k < EDGE_F; k++) {
            float4 w = *(const float4*)&sWe[k * IN_F + 4*j];
            a.x = fmaf(ef[k], w.x, a.x);
            a.y = fmaf(ef[k], w.y, a.y);
            a.z = fmaf(ef[k], w.z, a.z);
            a.w = fmaf(ef[k], w.w, a.w);
        }
        a.x = fmaxf(a.x, 0.f); a.y = fmaxf(a.y, 0.f);
        a.z = fmaxf(a.z, 0.f); a.w = fmaxf(a.w, 0.f);
        float4 nf = np[j];
        a.x *= nf.x; a.y *= nf.y; a.z *= nf.z; a.w *= nf.w;
        op[j] = a;
    }
}

// ---------------- gather0: h = [nfeat | mean(msg)] ----------------
__global__ void __launch_bounds__(256) k_gather0(const float* __restrict__ nfeat) {
    int gw   = (blockIdx.x * 256 + threadIdx.x) >> 5;
    int lane = threadIdx.x & 31;
    int half = lane >> 4, sub = lane & 15;
    int node = gw * 2 + half;
    if (node >= N_NODES) return;
    bool active = sub < (IN_F / 4);

    int lo = g_rowptr[node], hi = g_rowptr[node + 1];
    float4 a0 = make_float4(0.f,0.f,0.f,0.f), a1 = make_float4(0.f,0.f,0.f,0.f);
    if (active) {
        int p = lo;
        for (; p + 1 < hi; p += 2) {
            float4 v0 = *(const float4*)(g_msg + (size_t)p       * IN_F + sub * 4);
            float4 v1 = *(const float4*)(g_msg + (size_t)(p + 1) * IN_F + sub * 4);
            a0.x += v0.x; a0.y += v0.y; a0.z += v0.z; a0.w += v0.w;
            a1.x += v1.x; a1.y += v1.y; a1.z += v1.z; a1.w += v1.w;
        }
        if (p < hi) {
            float4 v = *(const float4*)(g_msg + (size_t)p * IN_F + sub * 4);
            a0.x += v.x; a0.y += v.y; a0.z += v.z; a0.w += v.w;
        }
    }
    if (active) {
        float invd = 1.0f / fmaxf((float)(hi - lo), 1.0f);
        float4 nf = *(const float4*)(nfeat + (size_t)node * IN_F + sub * 4);
        *(float4*)(g_h + (size_t)node * CAT_F + sub * 4) = nf;
        float4 acc;
        acc.x = (a0.x + a1.x) * invd; acc.y = (a0.y + a1.y) * invd;
        acc.z = (a0.z + a1.z) * invd; acc.w = (a0.w + a1.w) * invd;
        *(float4*)(g_h + (size_t)node * CAT_F + IN_F + sub * 4) = acc;
    }
}

// ---------------- gather1: hn1 = mean(h[src]) ----------------
__global__ void __launch_bounds__(256) k_gather_h() {
    int node = (blockIdx.x * 256 + threadIdx.x) >> 5;
    int lane = threadIdx.x & 31;
    if (node >= N_NODES) return;
    bool active = lane < (CAT_F / 4);

    int lo = g_rowptr[node], hi = g_rowptr[node + 1];
    float4 a0 = make_float4(0.f,0.f,0.f,0.f), a1 = make_float4(0.f,0.f,0.f,0.f);
    int p = lo;
    for (; p + 1 < hi; p += 2) {
        int s0 = g_csr_src[p], s1 = g_csr_src[p + 1];
        if (active) {
            float4 v0 = *(const float4*)(g_h + (size_t)s0 * CAT_F + lane * 4);
            float4 v1 = *(const float4*)(g_h + (size_t)s1 * CAT_F + lane * 4);
            a0.x += v0.x; a0.y += v0.y; a0.z += v0.z; a0.w += v0.w;
            a1.x += v1.x; a1.y += v1.y; a1.z += v1.z; a1.w += v1.w;
        }
    }
    if (p < hi) {
        int s = g_csr_src[p];
        if (active) {
            float4 v = *(const float4*)(g_h + (size_t)s * CAT_F + lane * 4);
            a0.x += v.x; a0.y += v.y; a0.z += v.z; a0.w += v.w;
        }
    }
    if (active) {
        float invd = 1.0f / fmaxf((float)(hi - lo), 1.0f);
        float4 acc;
        acc.x = (a0.x + a1.x) * invd; acc.y = (a0.y + a1.y) * invd;
        acc.z = (a0.z + a1.z) * invd; acc.w = (a0.w + a1.w) * invd;
        *(float4*)(g_hn1 + (size_t)node * CAT_F + lane * 4) = acc;
    }
}

// ---------------- SAGEConv1 (smem-W, grid-stride): h1 = relu(h@W1s + hn1@W1n + b1) ----------------
// dynamic smem: sW[192*128] + sB[128]
#define S1_SMEM ((192 * 128 + 128) * 4)
#define N_TILES64 ((N_NODES + 63) / 64)

__global__ void __launch_bounds__(256) k_sage1_s(const float* __restrict__ W1s,
                                                 const float* __restrict__ W1n,
                                                 const float* __restrict__ b1) {
    extern __shared__ float sW[];          // [192][128], rows 0..95 = W1s, 96..191 = W1n
    float* sB = sW + 192 * 128;
    for (int i = threadIdx.x; i < 96 * 128 / 4; i += 256) {
        ((float4*)sW)[i]                 = ((const float4*)W1s)[i];
        ((float4*)sW)[96 * 128 / 4 + i]  = ((const float4*)W1n)[i];
    }
    for (int i = threadIdx.x; i < 128; i += 256) sB[i] = b1[i];
    __syncthreads();

    int warp = threadIdx.x >> 5;
    int lane = threadIdx.x & 31;
    int c = lane * 4;

    for (int tile = blockIdx.x; tile < N_TILES64; tile += gridDim.x) {
        int n0 = tile * 64 + warp * 8;
        if (n0 >= N_NODES) continue;

        float acc[8][4];
        #pragma unroll
        for (int j = 0; j < 8; j++) { acc[j][0]=0.f; acc[j][1]=0.f; acc[j][2]=0.f; acc[j][3]=0.f; }

        #pragma unroll 1
        for (int hf = 0; hf < 2; hf++) {
            const float* xb = (hf == 0 ? g_h : g_hn1) + (size_t)n0 * CAT_F;
            const float* Ws = sW + hf * 96 * 128;
            #pragma unroll 1
            for (int k0 = 0; k0 < CAT_F; k0 += 4) {
                float4 xv[8];
                #pragma unroll
                for (int j = 0; j < 8; j++) xv[j] = *(const float4*)(xb + (size_t)j * CAT_F + k0);
                #pragma unroll
                for (int kk = 0; kk < 4; kk++) {
                    float4 w = *(const float4*)&Ws[(k0 + kk) * 128 + c];
                    #pragma unroll
                    for (int j = 0; j < 8; j++) {
                        float x = (kk == 0) ? xv[j].x : (kk == 1) ? xv[j].y : (kk == 2) ? xv[j].z : xv[j].w;
                        acc[j][0] = fmaf(x, w.x, acc[j][0]);
                        acc[j][1] = fmaf(x, w.y, acc[j][1]);
                        acc[j][2] = fmaf(x, w.z, acc[j][2]);
                        acc[j][3] = fmaf(x, w.w, acc[j][3]);
                    }
                }
            }
        }

        float4 b = *(const float4*)&sB[c];
        #pragma unroll
        for (int j = 0; j < 8; j++) {
            float4 r;
            r.x = fmaxf(acc[j][0] + b.x, 0.f);
            r.y = fmaxf(acc[j][1] + b.y, 0.f);
            r.z = fmaxf(acc[j][2] + b.z, 0.f);
            r.w = fmaxf(acc[j][3] + b.w, 0.f);
            *(float4*)(g_h1 + (size_t)(n0 + j) * HID_F + c) = r;
        }
    }
}

// ---------------- premul2 (smem-W, grid-stride): z2 = h1 @ W2n ----------------
__global__ void __launch_bounds__(256) k_premul2_s(const float* __restrict__ W2n) {
    __shared__ __align__(16) float sW[128 * 64];
    for (int i = threadIdx.x; i < 128 * 64 / 4; i += 256)
        ((float4*)sW)[i] = ((const float4*)W2n)[i];
    __syncthreads();

    int warp = threadIdx.x >> 5;
    int lane = threadIdx.x & 31;
    int c = lane * 2;

    for (int tile = blockIdx.x; tile < N_TILES64; tile += gridDim.x) {
        int n0 = tile * 64 + warp * 8;
        if (n0 >= N_NODES) continue;

        float acc[8][2];
        #pragma unroll
        for (int j = 0; j < 8; j++) { acc[j][0]=0.f; acc[j][1]=0.f; }

        const float* xb = g_h1 + (size_t)n0 * HID_F;
        #pragma unroll 1
        for (int k0 = 0; k0 < HID_F; k0 += 4) {
            float4 xv[8];
            #pragma unroll
            for (int j = 0; j < 8; j++) xv[j] = *(const float4*)(xb + (size_t)j * HID_F + k0);
            #pragma unroll
            for (int kk = 0; kk < 4; kk++) {
                float2 w = *(const float2*)&sW[(k0 + kk) * 64 + c];
                #pragma unroll
                for (int j = 0; j < 8; j++) {
                    float x = (kk == 0) ? xv[j].x : (kk == 1) ? xv[j].y : (kk == 2) ? xv[j].z : xv[j].w;
                    acc[j][0] = fmaf(x, w.x, acc[j][0]);
                    acc[j][1] = fmaf(x, w.y, acc[j][1]);
                }
            }
        }

        #pragma unroll
        for (int j = 0; j < 8; j++) {
            float2 r; r.x = acc[j][0]; r.y = acc[j][1];
            *(float2*)(g_z2 + (size_t)(n0 + j) * OUT_F + c) = r;
        }
    }
}

// ---------------- sage2 fused (smem-W, grid-stride): out = h1@W2s + mean(z2[src]) + b2 ----------------
__global__ void __launch_bounds__(256) k_sage2f_s(const float* __restrict__ W2s,
                                                  const float* __restrict__ b2,
                                                  float* __restrict__ out) {
    __shared__ __align__(16) float sW[128 * 64];
    __shared__ float sB[64];
    for (int i = threadIdx.x; i < 128 * 64 / 4; i += 256)
        ((float4*)sW)[i] = ((const float4*)W2s)[i];
    for (int i = threadIdx.x; i < 64; i += 256) sB[i] = b2[i];
    __syncthreads();

    int warp = threadIdx.x >> 5;
    int lane = threadIdx.x & 31;
    int c = lane * 2;

    for (int tile = blockIdx.x; tile < N_TILES64; tile += gridDim.x) {
        int n0 = tile * 64 + warp * 8;
        if (n0 >= N_NODES) continue;

        float acc[8][2];
        #pragma unroll
        for (int j = 0; j < 8; j++) { acc[j][0]=0.f; acc[j][1]=0.f; }

        const float* xb = g_h1 + (size_t)n0 * HID_F;
        #pragma unroll 1
        for (int k0 = 0; k0 < HID_F; k0 += 4) {
            float4 xv[8];
            #pragma unroll
            for (int j = 0; j < 8; j++) xv[j] = *(const float4*)(xb + (size_t)j * HID_F + k0);
            #pragma unroll
            for (int kk = 0; kk < 4; kk++) {
                float2 w = *(const float2*)&sW[(k0 + kk) * 64 + c];
                #pragma unroll
                for (int j = 0; j < 8; j++) {
                    float x = (kk == 0) ? xv[j].x : (kk == 1) ? xv[j].y : (kk == 2) ? xv[j].z : xv[j].w;
                    acc[j][0] = fmaf(x, w.x, acc[j][0]);
                    acc[j][1] = fmaf(x, w.y, acc[j][1]);
                }
            }
        }

        #pragma unroll 1
        for (int j = 0; j < 8; j++) {
            int node = n0 + j;
            int lo = g_rowptr[node], hi = g_rowptr[node + 1];
            float2 a0 = make_float2(0.f, 0.f), a1 = make_float2(0.f, 0.f);
            int p = lo;
            for (; p + 1 < hi; p += 2) {
                int s0 = g_csr_src[p], s1 = g_csr_src[p + 1];
                float2 v0 = *(const float2*)(g_z2 + (size_t)s0 * OUT_F + c);
                float2 v1 = *(const float2*)(g_z2 + (size_t)s1 * OUT_F + c);
                a0.x += v0.x; a0.y += v0.y;
                a1.x += v1.x; a1.y += v1.y;
            }
            if (p < hi) {
                int s = g_csr_src[p];
                float2 v = *(const float2*)(g_z2 + (size_t)s * OUT_F + c);
                a0.x += v.x; a0.y += v.y;
            }
            float invd = 1.0f / fmaxf((float)(hi - lo), 1.0f);
            acc[j][0] += (a0.x + a1.x) * invd;
            acc[j][1] += (a0.y + a1.y) * invd;
        }

        float2 b = *(const float2*)&sB[c];
        #pragma unroll
        for (int j = 0; j < 8; j++) {
            float2 r;
            r.x = acc[j][0] + b.x;
            r.y = acc[j][1] + b.y;
            *(float2*)(out + (size_t)(n0 + j) * OUT_F + c) = r;
        }
    }
}

extern "C" void kernel_launch(void* const* d_in, const int* in_sizes, int n_in,
                              void* d_out, int out_size) {
    const float* nfeat = (const float*)d_in[0];
    const float* efeat = (const float*)d_in[1];
    const int*   src   = (const int*)  d_in[2];
    const int*   dst   = (const int*)  d_in[3];
    const float* We    = (const float*)d_in[4];
    const float* be    = (const float*)d_in[5];
    const float* W1s   = (const float*)d_in[6];
    const float* W1n   = (const float*)d_in[7];
    const float* b1    = (const float*)d_in[8];
    const float* W2s   = (const float*)d_in[9];
    const float* W2n   = (const float*)d_in[10];
    const float* b2    = (const float*)d_in[11];
    float* out = (float*)d_out;

    const int TPB = 256;
    const int edge_blocks = (N_EDGES + TPB - 1) / TPB;
    const int node_blocks = (N_NODES + TPB - 1) / TPB;
    const int g0_blocks   = (N_NODES + 15) / 16;
    const int gw_blocks   = (N_NODES + 7) / 8;
    const int s1_blocks   = 296;   // 2 CTA/SM at 98KB smem
    const int s2_blocks   = 592;

    cudaFuncSetAttribute(k_sage1_s, cudaFuncAttributeMaxDynamicSharedMemorySize, S1_SMEM);

    k_zero_hist<<<node_blocks, TPB>>>();
    k_hist     <<<edge_blocks, TPB>>>(dst);
    k_scan     <<<1, SCAN_T>>>();
    k_place    <<<edge_blocks, TPB>>>(src, dst);
    k_edge_mlp <<<edge_blocks, TPB>>>(efeat, nfeat, We, be);
    k_gather0  <<<g0_blocks, TPB>>>(nfeat);
    k_gather_h <<<gw_blocks, TPB>>>();
    k_sage1_s  <<<s1_blocks, TPB, S1_SMEM>>>(W1s, W1n, b1);
    k_premul2_s<<<s2_blocks, TPB>>>(W2n);
    k_sage2f_s <<<s2_blocks, TPB>>>(W2s, b2, out);
}